// round 9
// baseline (speedup 1.0000x reference)
#include <cuda_runtime.h>

// ---------------- problem constants ----------------
constexpr int   kNumNodes   = 120000;
constexpr int   kNumMovable = 100000;
constexpr int   kNumNets    = 100000;
constexpr int   kNumPins    = 400000;
constexpr int   kNbx = 256, kNby = 256;
constexpr int   kMap = kNbx * kNby;
constexpr float kBsx = 1000.0f / 256.0f;      // 3.90625 (exact in fp32)
constexpr float kBsy = 1000.0f / 256.0f;
constexpr float kInvBsx = 256.0f / 1000.0f;
constexpr float kInvBsy = 256.0f / 1000.0f;
constexpr float kEps = 1e-6f;
constexpr float kBinArea = kBsx * kBsy;
constexpr float kHNorm = 1.0f / (kBinArea * 1.5f);   // UNIT_H_CAP
constexpr float kVNorm = 1.0f / (kBinArea * 1.5f);   // UNIT_V_CAP

// ---------------- device scratch (no allocs allowed) ----------------
// g_scat4[m*kMap + x*256 + y] = {A', Bx', By', P}; one red.v4 per corner.
// Zero-initialized at load; scan_y re-zeros it in place each run.
__device__ float4 g_scat4[2 * kMap];
// g_T: [U1h, U2h, U1v, U2v], each y-major [y*256+x]
__device__ float g_T[4 * kMap];
// per-cell {u, ry} where ry = exclusive x-prefix of util in the row; y-major
__device__ float2 g_uq[kMap];

__device__ __forceinline__ void red4(float4* p, float a, float b, float c, float d) {
    asm volatile("red.global.add.v4.f32 [%0], {%1, %2, %3, %4};"
                 :: "l"(p), "f"(a), "f"(b), "f"(c), "f"(d) : "memory");
}

// 8 lanes per net: parallel pin reduction, then EACH lane fires exactly one
// red.v4 for its (map, corner) slot -> scatter chain depth 1.
__global__ void net_kernel(const float* __restrict__ pin_pos,
                           const int* __restrict__ netpin_start,
                           const int* __restrict__ flat_netpin) {
    int t = blockIdx.x * blockDim.x + threadIdx.x;
    int n = t >> 3;               // net id
    int lane8 = threadIdx.x & 7;
    if (n >= kNumNets) return;    // aligned: whole 8-group exits together
    int s = netpin_start[n];
    int e = netpin_start[n + 1];

    float xmin = 1e30f, xmax = -1e30f, ymin = 1e30f, ymax = -1e30f;
    for (int p = s + lane8; p < e; p += 8) {
        int q    = __ldg(&flat_netpin[p]);
        float px = __ldg(&pin_pos[q]);
        float py = __ldg(&pin_pos[kNumPins + q]);
        xmin = fminf(xmin, px); xmax = fmaxf(xmax, px);
        ymin = fminf(ymin, py); ymax = fmaxf(ymax, py);
    }
    // width-8 subwarp reduction; all 8 lanes end with the full bbox
#pragma unroll
    for (int o = 4; o >= 1; o >>= 1) {
        xmin = fminf(xmin, __shfl_xor_sync(0xffffffffu, xmin, o, 8));
        xmax = fmaxf(xmax, __shfl_xor_sync(0xffffffffu, xmax, o, 8));
        ymin = fminf(ymin, __shfl_xor_sync(0xffffffffu, ymin, o, 8));
        ymax = fmaxf(ymax, __shfl_xor_sync(0xffffffffu, ymax, o, 8));
    }
    if (e <= s) return;           // empty net -> no contribution

    float span_x = xmax - xmin;
    float span_y = ymax - ymin;
    float ch = (span_y > kEps) ? (1.0f / fmaxf(span_y, kEps)) : 0.0f;
    float cv = (span_x > kEps) ? (1.0f / fmaxf(span_x, kEps)) : 0.0f;

    // lane l -> (map = l>>2, i = (l>>1)&1, j = l&1)
    int mp = lane8 >> 2;
    int ii = (lane8 >> 1) & 1;
    int jj = lane8 & 1;
    float coef = mp ? cv : ch;
    if (coef == 0.0f) return;
    float va = ii ? xmax : xmin;
    float vb = jj ? ymax : ymin;
    int ka = min(max(__float2int_rd(va * kInvBsx), 0), kNbx - 1);
    int kb = min(max(__float2int_rd(vb * kInvBsy), 0), kNby - 1);
    float fa = fminf(fmaxf(va - (float)ka * kBsx, 0.0f), kBsx);
    float fb = fminf(fmaxf(vb - (float)kb * kBsy, 0.0f), kBsy);
    float w  = (ii == jj) ? coef : -coef;
    red4(&g_scat4[mp * kMap + ka * kNby + kb],
         w * (kBsx * kBsy), w * kBsx * fb, w * fa * kBsy, w * fa * fb);
}

// Dual inclusive suffix scan over a 256-thread block.
__device__ __forceinline__ void dual_block_suffix_scan(float v1, float v2,
                                                       float& o1, float& o2) {
    __shared__ float s1[8], s2[8];
    int tid  = threadIdx.x;
    int lane = tid & 31;
    int w    = tid >> 5;
    float x1 = v1, x2 = v2;
#pragma unroll
    for (int o = 1; o < 32; o <<= 1) {
        float t1 = __shfl_down_sync(0xffffffffu, x1, o);
        float t2 = __shfl_down_sync(0xffffffffu, x2, o);
        if (lane + o < 32) { x1 += t1; x2 += t2; }
    }
    if (lane == 0) { s1[w] = x1; s2[w] = x2; }   // warp suffix totals
    __syncthreads();
    float a1 = 0.f, a2 = 0.f;
#pragma unroll
    for (int j = 0; j < 8; ++j) {
        if (j > w) { a1 += s1[j]; a2 += s2[j]; }
    }
    o1 = x1 + a1;
    o2 = x2 + a2;
}

// Forward EXCLUSIVE prefix scan of one value over a 256-thread block.
__device__ __forceinline__ float block_prefix_excl(float v) {
    __shared__ float ws[8];
    int lane = threadIdx.x & 31;
    int w    = threadIdx.x >> 5;
    float x = v;
#pragma unroll
    for (int o = 1; o < 32; o <<= 1) {
        float t = __shfl_up_sync(0xffffffffu, x, o);
        if (lane >= o) x += t;
    }
    if (lane == 31) ws[w] = x;   // warp inclusive totals
    __syncthreads();
    float add = 0.f;
#pragma unroll
    for (int j = 0; j < 8; ++j) {
        if (j < w) add += ws[j];
    }
    return (x - v) + add;        // exclusive
}

// Per (m, x) row: U1 = SyExcl(A') + Bx',  U2 = SyExcl(By') + P.
// Coalesced float4 read, in-place re-zero, transposed y-major store.
__global__ void scan_y_kernel() {
    int b = blockIdx.x;           // 0..511
    int m = b >> 8;
    int x = b & 255;
    int y = threadIdx.x;
    int ci = m * kMap + x * kNby + y;
    float4 c = g_scat4[ci];
    g_scat4[ci] = make_float4(0.f, 0.f, 0.f, 0.f);
    float sA, sBy;
    dual_block_suffix_scan(c.x, c.z, sA, sBy);     // inclusive
    float U1 = (sA  - c.x) + c.y;                  // exclusive + Bx'
    float U2 = (sBy - c.z) + c.w;                  // exclusive + P
    float* T1 = g_T + m * 2 * kMap;                // y-major
    float* T2 = T1 + kMap;
    int ti = y * kNbx + x;
    T1[ti] = U1;
    T2[ti] = U2;
}

// Per y column: H = SxExcl(U1h) + U2h, V likewise; fused util map.
// Also computes the exclusive x-prefix of util (the block holds the whole
// x-row) and stores {u, ry} per cell.
__global__ void scan_x_util_kernel() {
    int y = blockIdx.x;
    int x = threadIdx.x;
    int idx = y * kNbx + x;
    float u1h = g_T[idx];
    float u2h = g_T[kMap + idx];
    float u1v = g_T[2 * kMap + idx];
    float u2v = g_T[3 * kMap + idx];
    float sH, sV;
    dual_block_suffix_scan(u1h, u1v, sH, sV);      // inclusive
    float H = (sH - u1h) + u2h;                    // exclusive + U2
    float V = (sV - u1v) + u2v;
    float u = fmaxf(H * kHNorm, V * kVNorm);
    u = fminf(fmaxf(u, 0.5f), 2.0f);
    __syncthreads();                               // smem reuse barrier
    float ry = block_prefix_excl(u);
    g_uq[idx] = make_float2(u, ry);
}

// One thread per node. X-dimension handled analytically via the per-row
// antiderivative U(x) = bs*ry[kx] + fx*u[kx]:
//   row integral over [xl,xh] = U(xh) - U(xl)   (2 gathers instead of 4)
// Y handled explicitly over <=3 rows (node_size_y < 4 < 2*bs).
__global__ void node_kernel(const float* __restrict__ pos,
                            const float* __restrict__ nsx,
                            const float* __restrict__ nsy,
                            float* __restrict__ out) {
    int m = blockIdx.x * blockDim.x + threadIdx.x;
    if (m >= kNumMovable) return;
    float xl = pos[m];
    float yl = pos[kNumNodes + m];
    float xh = xl + nsx[m];
    float yh = yl + nsy[m];

    int kxl = min(max(__float2int_rd(xl * kInvBsx), 0), kNbx - 1);
    int kxh = min(max(__float2int_rd(xh * kInvBsx), 0), kNbx - 1);
    float fxl = fminf(fmaxf(xl - (float)kxl * kBsx, 0.0f), kBsx);
    float fxh = fminf(fmaxf(xh - (float)kxh * kBsx, 0.0f), kBsx);
    int by0 = min(max(__float2int_rd(yl * kInvBsy), 0), kNby - 1);

    // oy weights for the (at most) 3 rows
    float oy[3];
#pragma unroll
    for (int j = 0; j < 3; ++j) {
        float ey = (float)(by0 + j) * kBsy;
        oy[j] = fmaxf(fminf(yh, ey + kBsy) - fmaxf(yl, ey), 0.0f);
    }

    // 6 independent float2 gathers (2 per row)
    float2 ql[3], qh[3];
#pragma unroll
    for (int j = 0; j < 3; ++j) {
        int yb = min(by0 + j, kNby - 1);
        const float2* qrow = g_uq + yb * kNbx;
        ql[j] = __ldg(&qrow[kxl]);
        qh[j] = __ldg(&qrow[kxh]);
    }

    float acc = 0.0f;
#pragma unroll
    for (int j = 0; j < 3; ++j) {
        float row = kBsx * (qh[j].y - ql[j].y) + fxh * qh[j].x - fxl * ql[j].x;
        acc += oy[j] * row;
    }
    out[m] = acc;
}

// ---------------- launcher ----------------
extern "C" void kernel_launch(void* const* d_in, const int* in_sizes, int n_in,
                              void* d_out, int out_size) {
    const float* pos          = (const float*)d_in[0];
    const float* pin_pos      = (const float*)d_in[1];
    const float* node_size_x  = (const float*)d_in[2];
    const float* node_size_y  = (const float*)d_in[3];
    const int*   netpin_start = (const int*)d_in[4];
    const int*   flat_netpin  = (const int*)d_in[5];
    float*       out          = (float*)d_out;

    net_kernel<<<(kNumNets * 8 + 255) / 256, 256>>>(pin_pos, netpin_start, flat_netpin);
    scan_y_kernel<<<512, 256>>>();
    scan_x_util_kernel<<<256, 256>>>();
    node_kernel<<<(kNumMovable + 255) / 256, 256>>>(pos, node_size_x, node_size_y, out);
}